// round 2
// baseline (speedup 1.0000x reference)
#include <cuda_runtime.h>
#include <math.h>

// Problem constants (fixed by the reference)
#define Bc 8
#define Sc 64
#define Nc 1024
#define Cc 16
#define Hc 128
#define Pc 10
#define MAXN 128   // max neighbors kept per row (3% of 1024 ~= 31, >17-sigma margin)

// ---------------------------------------------------------------------------
// Device-global scratch (allocation-free rule: __device__ arrays only)
// ---------------------------------------------------------------------------
__device__ float g_sol[Pc * Bc * Nc * Hc];   // [P,B,N,H] trajectory (40 MB)
__device__ float g_logits[Bc * Nc];
__device__ float g_attn[Bc * Nc];
__device__ int   g_nbr[Nc * MAXN];
__device__ int   g_cnt[Nc];
__device__ float g_inv[Nc];                  // 1/(rowsum + 1e-8)

// ---------------------------------------------------------------------------
// Helpers
// ---------------------------------------------------------------------------
__device__ __forceinline__ float nn_f(float x) {
    if (isnan(x)) return 0.0f;
    return fminf(fmaxf(x, -3.402823466e38f), 3.402823466e38f);
}

__device__ __forceinline__ float silu_f(float v) {
    return v / (1.0f + expf(-v));
}

// block of 128 threads: reduce (a,b) to block-wide sums, broadcast to all
__device__ __forceinline__ void red2_128(float& a, float& b, float* sm) {
#pragma unroll
    for (int o = 16; o > 0; o >>= 1) {
        a += __shfl_xor_sync(0xffffffffu, a, o);
        b += __shfl_xor_sync(0xffffffffu, b, o);
    }
    int w = threadIdx.x >> 5;
    if ((threadIdx.x & 31) == 0) { sm[w] = a; sm[4 + w] = b; }
    __syncthreads();
    a = sm[0] + sm[1] + sm[2] + sm[3];
    b = sm[4] + sm[5] + sm[6] + sm[7];
    __syncthreads();
}

// ---------------------------------------------------------------------------
// CSR build: one warp per adjacency row. Deterministic order via ballot/popc.
// ---------------------------------------------------------------------------
__global__ void build_csr_kernel(const float* __restrict__ adj) {
    int m = blockIdx.x * (blockDim.x >> 5) + (threadIdx.x >> 5);
    int lane = threadIdx.x & 31;
    if (m >= Nc) return;
    float rsum = 0.0f;
    int cnt = 0;
    for (int base = 0; base < Nc; base += 32) {
        float a = adj[m * Nc + base + lane];
        rsum += a;
        unsigned mask = __ballot_sync(0xffffffffu, a > 0.0f);
        if (a > 0.0f) {
            int pos = cnt + __popc(mask & ((1u << lane) - 1u));
            if (pos < MAXN) g_nbr[m * MAXN + pos] = base + lane;
        }
        cnt += __popc(mask);
    }
#pragma unroll
    for (int o = 16; o > 0; o >>= 1) rsum += __shfl_xor_sync(0xffffffffu, rsum, o);
    if (lane == 0) {
        g_cnt[m] = cnt < MAXN ? cnt : MAXN;
        g_inv[m] = 1.0f / (rsum + 1e-8f);
    }
}

// ---------------------------------------------------------------------------
// Encoder: z0 = silu(LN(x[:,0] @ enc_w + enc_b)) -> g_sol[0]; fused logits.
// grid (N, B), 128 threads
// ---------------------------------------------------------------------------
__global__ void enc_kernel(const float* __restrict__ x,
                           const float* __restrict__ w, const float* __restrict__ bb,
                           const float* __restrict__ g, const float* __restrict__ beta,
                           const float* __restrict__ attn_w,
                           const float* __restrict__ attn_b) {
    int n = blockIdx.x, b = blockIdx.y, j = threadIdx.x;
    __shared__ float xr[Cc];
    __shared__ float red[8];
    if (j < Cc) xr[j] = x[((size_t)b * Sc * Nc + n) * Cc + j];
    __syncthreads();
    float u = bb[j];
#pragma unroll
    for (int c = 0; c < Cc; c++) u += xr[c] * w[c * Hc + j];
    float s1 = u, s2 = u * u;
    red2_128(s1, s2, red);
    float mean = s1 * (1.0f / Hc);
    float var  = s2 * (1.0f / Hc) - mean * mean;
    float ln = (u - mean) * rsqrtf(var + 1e-5f) * g[j] + beta[j];
    float z = silu_f(ln);
    g_sol[((size_t)b * Nc + n) * Hc + j] = z;
    // fused logits for step 1's softmax
    float la = z * attn_w[j], lz = 0.0f;
    red2_128(la, lz, red);
    if (j == 0) g_logits[b * Nc + n] = la + attn_b[0];
}

// ---------------------------------------------------------------------------
// Softmax over nodes, per batch. one block (256 thr) per batch
// ---------------------------------------------------------------------------
__global__ void softmax_kernel() {
    int b = blockIdx.x, t = threadIdx.x;
    __shared__ float sm[8];
    __shared__ float bcast;
    float mx = -3.4e38f;
    for (int n = t; n < Nc; n += 256) mx = fmaxf(mx, g_logits[b * Nc + n]);
#pragma unroll
    for (int o = 16; o > 0; o >>= 1) mx = fmaxf(mx, __shfl_xor_sync(0xffffffffu, mx, o));
    if ((t & 31) == 0) sm[t >> 5] = mx;
    __syncthreads();
    if (t == 0) {
        float m2 = sm[0];
        for (int w = 1; w < 8; w++) m2 = fmaxf(m2, sm[w]);
        bcast = m2;
    }
    __syncthreads();
    float bmax = bcast;
    float sum = 0.0f;
    for (int n = t; n < Nc; n += 256) {
        float e = expf(g_logits[b * Nc + n] - bmax);
        g_attn[b * Nc + n] = e;
        sum += e;
    }
#pragma unroll
    for (int o = 16; o > 0; o >>= 1) sum += __shfl_xor_sync(0xffffffffu, sum, o);
    __syncthreads();
    if ((t & 31) == 0) sm[t >> 5] = sum;
    __syncthreads();
    if (t == 0) {
        float s2 = 0.0f;
        for (int w = 0; w < 8; w++) s2 += sm[w];
        bcast = 1.0f / s2;
    }
    __syncthreads();
    float inv = bcast;
    for (int n = t; n < Nc; n += 256) g_attn[b * Nc + n] *= inv;
}

// ---------------------------------------------------------------------------
// One Euler step, ALL 8 batches of one node per block (weights amortized 8x).
// grid (N), 128 threads. Fused logits epilogue for the next softmax.
// ---------------------------------------------------------------------------
__global__ void step_kernel(const float* __restrict__ w1, const float* __restrict__ b1,
                            const float* __restrict__ g,  const float* __restrict__ beta,
                            const float* __restrict__ w2, const float* __restrict__ b2,
                            const float* __restrict__ diff_scale,
                            const float* __restrict__ time_scale,
                            const float* __restrict__ attn_w,
                            const float* __restrict__ attn_b, int p) {
    int m = blockIdx.x, j = threadIdx.x;
    int wid = j >> 5, lane = j & 31;
    const float* s_in  = g_sol + (size_t)(p - 1) * Bc * Nc * Hc;
    float*       s_out = g_sol + (size_t)p       * Bc * Nc * Hc;

    __shared__ float srow[Bc][Hc + 4];
    __shared__ float h1[Bc][Hc + 4];
    __shared__ float red4[4][Bc];
    __shared__ float smean[Bc], srstd[Bc];
    __shared__ float coef[Bc][MAXN];
    __shared__ int   nidx[MAXN];

    int   cnt = g_cnt[m];
    float inv = g_inv[m];
    if (j < cnt) {
        int nb = g_nbr[m * MAXN + j];
        nidx[j] = nb;
#pragma unroll
        for (int r = 0; r < Bc; r++) coef[r][j] = g_attn[r * Nc + nb] * inv;
    }
#pragma unroll
    for (int r = 0; r < Bc; r++)
        srow[r][j] = nn_f(s_in[((size_t)r * Nc + m) * Hc + j]);
    __syncthreads();

    // dyn layer 1: u = s @ W1 + b1 (8 rows at once)
    float acc[Bc];
#pragma unroll
    for (int r = 0; r < Bc; r++) acc[r] = b1[j];
    for (int k = 0; k < Hc; k++) {
        float w = __ldg(&w1[k * Hc + j]);
#pragma unroll
        for (int r = 0; r < Bc; r++) acc[r] += srow[r][k] * w;
    }
#pragma unroll
    for (int r = 0; r < Bc; r++) h1[r][j] = acc[r];
    __syncthreads();

    // LN stats: each warp owns 2 rows
#pragma unroll
    for (int rr = 0; rr < 2; rr++) {
        int r = wid * 2 + rr;
        float s1 = 0.0f, s2 = 0.0f;
#pragma unroll
        for (int kk = lane; kk < Hc; kk += 32) {
            float v = h1[r][kk];
            s1 += v; s2 += v * v;
        }
#pragma unroll
        for (int o = 16; o > 0; o >>= 1) {
            s1 += __shfl_xor_sync(0xffffffffu, s1, o);
            s2 += __shfl_xor_sync(0xffffffffu, s2, o);
        }
        if (lane == 0) {
            float mean = s1 * (1.0f / Hc);
            float var  = s2 * (1.0f / Hc) - mean * mean;
            smean[r] = mean;
            srstd[r] = rsqrtf(var + 1e-5f);
        }
    }
    __syncthreads();
#pragma unroll
    for (int r = 0; r < Bc; r++)
        h1[r][j] = silu_f((acc[r] - smean[r]) * srstd[r] * g[j] + beta[j]);
    __syncthreads();

    // dyn layer 2: tanh(h1 @ W2 + b2)
    float d[Bc];
#pragma unroll
    for (int r = 0; r < Bc; r++) d[r] = b2[j];
    for (int k = 0; k < Hc; k++) {
        float w = __ldg(&w2[k * Hc + j]);
#pragma unroll
        for (int r = 0; r < Bc; r++) d[r] += h1[r][k] * w;
    }

    // diffusion: (1/deg) * sum_{n in nbr(m)} attn[b,n] * nan_to_num(s[b,n,:])
    float dv[Bc];
#pragma unroll
    for (int r = 0; r < Bc; r++) dv[r] = 0.0f;
    for (int k = 0; k < cnt; k++) {
        int nb = nidx[k];
#pragma unroll
        for (int r = 0; r < Bc; r++)
            dv[r] += coef[r][k] * nn_f(s_in[((size_t)r * Nc + nb) * Hc + j]);
    }

    float ds = diff_scale[0], ts = time_scale[0];
    float dx[Bc];
#pragma unroll
    for (int r = 0; r < Bc; r++) dx[r] = ts * (tanhf(d[r]) + dv[r] * ds);

    // norm clamp per row: block-wide sum of dx^2 per r
    float q[Bc];
#pragma unroll
    for (int r = 0; r < Bc; r++) q[r] = dx[r] * dx[r];
#pragma unroll
    for (int o = 16; o > 0; o >>= 1)
#pragma unroll
        for (int r = 0; r < Bc; r++) q[r] += __shfl_xor_sync(0xffffffffu, q[r], o);
    if (lane == 0) {
#pragma unroll
        for (int r = 0; r < Bc; r++) red4[wid][r] = q[r];
    }
    __syncthreads();

    float la[Bc];
    float aw = attn_w[j];
#pragma unroll
    for (int r = 0; r < Bc; r++) {
        float nr = sqrtf(red4[0][r] + red4[1][r] + red4[2][r] + red4[3][r]);
        float sc = fminf(10.0f / (nr + 1e-8f), 1.0f);
        float o  = srow[r][j] + nn_f(dx[r] * sc) * 7.0f;
        s_out[((size_t)r * Nc + m) * Hc + j] = o;
        la[r] = o * aw;
    }
    // fused logits epilogue (for next softmax; wasted on last step, harmless)
#pragma unroll
    for (int o = 16; o > 0; o >>= 1)
#pragma unroll
        for (int r = 0; r < Bc; r++) la[r] += __shfl_xor_sync(0xffffffffu, la[r], o);
    if (lane == 0) {
#pragma unroll
        for (int r = 0; r < Bc; r++) red4[wid][r] = la[r];
    }
    __syncthreads();
    if (j < Bc)
        g_logits[j * Nc + m] = red4[0][j] + red4[1][j] + red4[2][j] + red4[3][j]
                             + attn_b[0];
}

// ---------------------------------------------------------------------------
// Interp + decoder, 8 time-steps per block (weight-load amortization).
// grid (N, B, 8 groups of 8 time steps), 128 threads.
// ---------------------------------------------------------------------------
__global__ void decode_kernel(const float* __restrict__ w1, const float* __restrict__ b1,
                              const float* __restrict__ g,  const float* __restrict__ beta,
                              const float* __restrict__ w2, const float* __restrict__ b2,
                              float* __restrict__ pred, float* __restrict__ interp) {
    int n = blockIdx.x, b = blockIdx.y, sg = blockIdx.z, j = threadIdx.x;
    __shared__ float zs[8][132];
    __shared__ float hs[8][132];
    __shared__ float smean[8], srstd[8];

    size_t base = ((size_t)b * Nc + n) * Hc + j;
#pragma unroll
    for (int r = 0; r < 8; r++) {
        int si = sg * 8 + r;
        int ic = (si + 6) / 7;        // ceil(si/7)
        if (ic < 1) ic = 1;
        float alpha = (float)(si - 7 * (ic - 1)) * (1.0f / 7.0f);
        float a0 = g_sol[(size_t)(ic - 1) * Bc * Nc * Hc + base];
        float a1 = g_sol[(size_t)ic       * Bc * Nc * Hc + base];
        float z = (1.0f - alpha) * a0 + alpha * a1;
        zs[r][j] = z;
        if (interp) interp[(((size_t)si * Bc + b) * Nc + n) * Hc + j] = z;
    }
    __syncthreads();

    // u = z @ dec_w1 + b1 for 8 rows at once
    float acc[8];
#pragma unroll
    for (int r = 0; r < 8; r++) acc[r] = b1[j];
    for (int k = 0; k < Hc; k++) {
        float w = __ldg(&w1[k * Hc + j]);
#pragma unroll
        for (int r = 0; r < 8; r++) acc[r] += zs[r][k] * w;
    }
#pragma unroll
    for (int r = 0; r < 8; r++) hs[r][j] = acc[r];
    __syncthreads();

    // LN stats: each warp owns 2 rows
    int wid = j >> 5, lane = j & 31;
#pragma unroll
    for (int rr = 0; rr < 2; rr++) {
        int r = wid * 2 + rr;
        float s1 = 0.0f, s2 = 0.0f;
#pragma unroll
        for (int kk = lane; kk < Hc; kk += 32) {
            float v = hs[r][kk];
            s1 += v; s2 += v * v;
        }
#pragma unroll
        for (int o = 16; o > 0; o >>= 1) {
            s1 += __shfl_xor_sync(0xffffffffu, s1, o);
            s2 += __shfl_xor_sync(0xffffffffu, s2, o);
        }
        if (lane == 0) {
            float mean = s1 * (1.0f / Hc);
            float var  = s2 * (1.0f / Hc) - mean * mean;
            smean[r] = mean;
            srstd[r] = rsqrtf(var + 1e-5f);
        }
    }
    __syncthreads();

#pragma unroll
    for (int r = 0; r < 8; r++) {
        float v = (hs[r][j] - smean[r]) * srstd[r] * g[j] + beta[j];
        zs[r][j] = silu_f(v);   // reuse zs as h
    }
    __syncthreads();

    if (pred) {
        int r = j >> 4, c = j & 15;   // 8 rows x 16 cols
        float pv = b2[c];
#pragma unroll 4
        for (int k = 0; k < Hc; k++) pv += zs[r][k] * __ldg(&w2[k * Cc + c]);
        int si = sg * 8 + r;
        pred[(((size_t)b * Sc + si) * Nc + n) * Cc + c] = pv;
    }
}

// ---------------------------------------------------------------------------
// Launch
// ---------------------------------------------------------------------------
extern "C" void kernel_launch(void* const* d_in, const int* in_sizes, int n_in,
                              void* d_out, int out_size) {
    const float* x        = (const float*)d_in[0];
    const float* adj      = (const float*)d_in[1];
    const float* enc_w    = (const float*)d_in[2];
    const float* enc_b    = (const float*)d_in[3];
    const float* enc_g    = (const float*)d_in[4];
    const float* enc_beta = (const float*)d_in[5];
    const float* dyn_w1   = (const float*)d_in[6];
    const float* dyn_b1   = (const float*)d_in[7];
    const float* dyn_g    = (const float*)d_in[8];
    const float* dyn_beta = (const float*)d_in[9];
    const float* dyn_w2   = (const float*)d_in[10];
    const float* dyn_b2   = (const float*)d_in[11];
    const float* attn_w   = (const float*)d_in[12];
    const float* attn_b   = (const float*)d_in[13];
    const float* diff_sc  = (const float*)d_in[14];
    const float* time_sc  = (const float*)d_in[15];
    const float* dec_w1   = (const float*)d_in[16];
    const float* dec_b1   = (const float*)d_in[17];
    const float* dec_g    = (const float*)d_in[18];
    const float* dec_beta = (const float*)d_in[19];
    const float* dec_w2   = (const float*)d_in[20];
    const float* dec_b2   = (const float*)d_in[21];

    float* out = (float*)d_out;
    const long long PRED_SZ   = (long long)Bc * Sc * Nc * Cc;   //  8388608
    const long long INTERP_SZ = (long long)Sc * Bc * Nc * Hc;   // 67108864
    float* pred_ptr = nullptr;
    float* interp_ptr = nullptr;
    long long osz = (long long)out_size;
    if (osz >= PRED_SZ + INTERP_SZ) { pred_ptr = out; interp_ptr = out + PRED_SZ; }
    else if (osz == INTERP_SZ)      { interp_ptr = out; }
    else                            { pred_ptr = out; }

    build_csr_kernel<<<Nc / 8, 256>>>(adj);
    enc_kernel<<<dim3(Nc, Bc), 128>>>(x, enc_w, enc_b, enc_g, enc_beta,
                                      attn_w, attn_b);

    for (int p = 1; p < Pc; p++) {
        softmax_kernel<<<Bc, 256>>>();
        step_kernel<<<Nc, 128>>>(dyn_w1, dyn_b1, dyn_g, dyn_beta,
                                 dyn_w2, dyn_b2, diff_sc, time_sc,
                                 attn_w, attn_b, p);
    }

    decode_kernel<<<dim3(Nc, Bc, 8), 128>>>(dec_w1, dec_b1, dec_g, dec_beta,
                                            dec_w2, dec_b2, pred_ptr, interp_ptr);
}